// round 2
// baseline (speedup 1.0000x reference)
#include <cuda_runtime.h>

// ---------------- problem constants ----------------
#define NB   64      // batch
#define DIN  768
#define HD   256
#define H2   512     // 2*HD
#define RT   24
#define RMM  16
#define RAA  8
#define NC   24      // control points
#define WOUT 512     // spline output size (H_OUT == W_OUT == 512)

// ---------------- scratch (device globals; no runtime alloc) ----------------
__device__ float g_hid[NB * H2];                 // trunk hidden [b][h2]
__device__ float g_shared_t[HD * NB];            // shared feat TRANSPOSED [c][b]
__device__ float g_rf_t[RT * HD * NB];           // rank feats TRANSPOSED [r][h][b]
__device__ float g_cp[4 * NB * 16 * NC];         // [gen][b][r][c], gen: 0=Pxm 1=Pym 2=Pxa 3=Pya
__device__ float g_u[NB * RMM * WOUT];           // u splines [b][r][w]
__device__ float g_v[NB * RMM * WOUT];           // v splines pre-scaled by softmax(mult_w)[r]
__device__ float g_dx[NB * WOUT];                // dx[b][w]
__device__ float g_dy[NB * WOUT];                // dy[b][h] + gbias folded in

// ---------------- helpers ----------------
typedef unsigned long long ull;

__device__ __forceinline__ ull pk2(float x, float y) {
    ull r; asm("mov.b64 %0, {%1,%2};" : "=l"(r) : "f"(x), "f"(y)); return r;
}
__device__ __forceinline__ void fma2(ull& d, ull a, ull b) {
    asm("fma.rn.f32x2 %0, %1, %2, %0;" : "+l"(d) : "l"(a), "l"(b));
}
__device__ __forceinline__ float2 up2(ull a) {
    float2 r; asm("mov.b64 {%0,%1}, %2;" : "=f"(r.x), "=f"(r.y) : "l"(a)); return r;
}
__device__ __forceinline__ float lk(float x) { return x >= 0.f ? x : 0.2f * x; }

// Hermite spline coefficients for output index w (out size 512, N=24 cps, nseg=23)
__device__ __forceinline__ void hcoef(int w, int& seg,
                                      float& h00, float& h10, float& h01, float& h11) {
    const float step = 0.998f / 511.f;       // (1-2*eps)/(out-1), eps=0.001
    float t  = 0.001f + (float)w * step;
    float ts = t * 23.f;
    int s = (int)floorf(ts);
    s = s < 0 ? 0 : (s > 22 ? 22 : s);
    float tau = ts - (float)s;
    tau = fminf(fmaxf(tau, 0.f), 0.9999f);
    float t2 = tau * tau, t3 = t2 * tau;
    h00 = 2.f * t3 - 3.f * t2 + 1.f;
    h10 = t3 - 2.f * t2 + tau;
    h01 = -2.f * t3 + 3.f * t2;
    h11 = t3 - t2;
    seg = s;
}
__device__ __forceinline__ float hermev(const float* cp, int s,
                                        float h00, float h10, float h01, float h11) {
    const float inv = 0.5f / 23.f;           // 0.5 / nseg
    float pk  = cp[s];
    float pk1 = cp[s + 1];
    int jm = s - 1; if (jm < 0) jm = 0;
    float mk = (cp[s + 1] - cp[jm]) * inv;   // m[s]   (s+1 <= 23 always)
    int j2 = s + 2; if (j2 > 23) j2 = 23;
    float mk1 = (cp[j2] - cp[s]) * inv;      // m[s+1]
    return h00 * pk + h10 * mk + h01 * pk1 + h11 * mk1;
}

// ---------------- K1a: hidden = leaky(h @ st_w1 + st_b1) ----------------
// grid (8 h-chunks of 64, 8 b-tiles of 8), block 256
__global__ void __launch_bounds__(256) k1a(const float* __restrict__ hin,
                                           const float* __restrict__ w1,
                                           const float* __restrict__ b1) {
    __shared__ __align__(16) float hs[8 * DIN];  // 24 KB
    int tid = threadIdx.x;
    int hc = blockIdx.x, btile = blockIdx.y;
    for (int i = tid; i < 8 * DIN; i += 256) hs[i] = hin[btile * 8 * DIN + i];
    __syncthreads();
    int hcol = hc * 64 + (tid & 63);
    int bl   = (tid >> 6) * 2;
    const float* w1p = w1 + hcol;
    const float* x0  = hs + bl * DIN;
    const float* x1  = x0 + DIN;
    float a0 = 0.f, a1 = 0.f;
#pragma unroll 4
    for (int d = 0; d < DIN; d++) {
        float w = w1p[d * H2];
        a0 = fmaf(w, x0[d], a0);
        a1 = fmaf(w, x1[d], a1);
    }
    float bias = b1[hcol];
    g_hid[(btile * 8 + bl) * H2 + hcol]     = lk(a0 + bias);
    g_hid[(btile * 8 + bl + 1) * H2 + hcol] = lk(a1 + bias);
}

// ---------------- K1b: shared_t[c][b] = hidden @ st_w2 + st_b2 ----------------
// grid (4 c-chunks of 64, 8 b-tiles of 8), block 256
__global__ void __launch_bounds__(256) k1b(const float* __restrict__ w2,
                                           const float* __restrict__ b2) {
    __shared__ __align__(16) float hs[8 * H2];   // 16 KB
    int tid = threadIdx.x;
    int cc = blockIdx.x, btile = blockIdx.y;
    for (int i = tid; i < 8 * H2; i += 256) hs[i] = g_hid[btile * 8 * H2 + i];
    __syncthreads();
    int c  = cc * 64 + (tid & 63);
    int bl = (tid >> 6) * 2;
    const float* wp = w2 + c;
    const float* x0 = hs + bl * H2;
    const float* x1 = x0 + H2;
    float a0 = 0.f, a1 = 0.f;
#pragma unroll 4
    for (int k = 0; k < H2; k++) {
        float w = wp[k * HD];
        a0 = fmaf(w, x0[k], a0);
        a1 = fmaf(w, x1[k], a1);
    }
    float bias = b2[c];
    g_shared_t[c * NB + btile * 8 + bl]     = a0 + bias;
    g_shared_t[c * NB + btile * 8 + bl + 1] = a1 + bias;
}

// ---------------- K2: rank feature gens (all 24 ranks) ----------------
// grid (4 b-tiles of 16, 24 ranks), block 256 (thread = output column h)
// comb_t[d][bb] padded to stride 20 (16B-aligned float4 rows); hdn overlays comb.
__global__ void __launch_bounds__(256) k2(const float* __restrict__ remb,
                                          const float* __restrict__ w1,
                                          const float* __restrict__ b1,
                                          const float* __restrict__ w2,
                                          const float* __restrict__ b2) {
    __shared__ __align__(16) float comb[H2 * 20];  // 40 KB
    int tid = threadIdx.x;
    int btile = blockIdx.x, r = blockIdx.y;
    int b0 = btile * 16;

    for (int i = tid; i < H2 * 16; i += 256) {
        int d = i >> 4, bb = i & 15;
        float v = (d < HD) ? g_shared_t[d * NB + b0 + bb] : remb[r * HD + (d - HD)];
        comb[d * 20 + bb] = v;
    }
    __syncthreads();

    ull acc[8];
#pragma unroll
    for (int j = 0; j < 8; j++) acc[j] = 0ull;
    const float* w1p = w1 + r * H2 * HD + tid;
#pragma unroll 4
    for (int d = 0; d < H2; d++) {
        float w = w1p[d * HD];
        ull wp = pk2(w, w);
        const float4* xr = (const float4*)(comb + d * 20);
        float4 x0 = xr[0], x1 = xr[1], x2 = xr[2], x3 = xr[3];
        fma2(acc[0], wp, pk2(x0.x, x0.y)); fma2(acc[1], wp, pk2(x0.z, x0.w));
        fma2(acc[2], wp, pk2(x1.x, x1.y)); fma2(acc[3], wp, pk2(x1.z, x1.w));
        fma2(acc[4], wp, pk2(x2.x, x2.y)); fma2(acc[5], wp, pk2(x2.z, x2.w));
        fma2(acc[6], wp, pk2(x3.x, x3.y)); fma2(acc[7], wp, pk2(x3.z, x3.w));
    }
    __syncthreads();                          // everyone done reading comb

    float bias = b1[r * HD + tid];
    float* hdn = comb;                        // overlay: [k][bb] stride 20
#pragma unroll
    for (int j = 0; j < 8; j++) {
        float2 p = up2(acc[j]);
        float2 o = make_float2(lk(p.x + bias), lk(p.y + bias));
        *(float2*)(hdn + tid * 20 + 2 * j) = o;
    }
    __syncthreads();

#pragma unroll
    for (int j = 0; j < 8; j++) acc[j] = 0ull;
    const float* w2p = w2 + r * HD * HD + tid;
#pragma unroll 4
    for (int k = 0; k < HD; k++) {
        float w = w2p[k * HD];
        ull wp = pk2(w, w);
        const float4* xr = (const float4*)(hdn + k * 20);
        float4 x0 = xr[0], x1 = xr[1], x2 = xr[2], x3 = xr[3];
        fma2(acc[0], wp, pk2(x0.x, x0.y)); fma2(acc[1], wp, pk2(x0.z, x0.w));
        fma2(acc[2], wp, pk2(x1.x, x1.y)); fma2(acc[3], wp, pk2(x1.z, x1.w));
        fma2(acc[4], wp, pk2(x2.x, x2.y)); fma2(acc[5], wp, pk2(x2.z, x2.w));
        fma2(acc[6], wp, pk2(x3.x, x3.y)); fma2(acc[7], wp, pk2(x3.z, x3.w));
    }
    float bias2 = b2[r * HD + tid];
    float* o = g_rf_t + (r * HD + tid) * NB + b0;
#pragma unroll
    for (int j = 0; j < 8; j++) {
        float2 p = up2(acc[j]);
        *(float2*)(o + 2 * j) = make_float2(p.x + bias2, p.y + bias2);
    }
}

// ---------------- K3: control-point gens (mx/my/ax/ay), 48 units ----------------
// grid (4 b-tiles of 16, 48 units), block 256
__global__ void __launch_bounds__(256) k3(
        const float* __restrict__ mxw1, const float* __restrict__ mxb1,
        const float* __restrict__ mxw2, const float* __restrict__ mxb2,
        const float* __restrict__ myw1, const float* __restrict__ myb1,
        const float* __restrict__ myw2, const float* __restrict__ myb2,
        const float* __restrict__ axw1, const float* __restrict__ axb1,
        const float* __restrict__ axw2, const float* __restrict__ axb2,
        const float* __restrict__ ayw1, const float* __restrict__ ayb1,
        const float* __restrict__ ayw2, const float* __restrict__ ayb2) {
    __shared__ __align__(16) float fin[HD * 20];   // 20 KB
    __shared__ __align__(16) float hdn[HD * 20];   // 20 KB
    int tid = threadIdx.x;
    int btile = blockIdx.x, u = blockIdx.y;
    int b0 = btile * 16;

    const float *w1, *b1, *w2, *b2;
    int r, src_r, gen;
    if (u < 16)      { r = u;      src_r = u;      gen = 0; w1 = mxw1; b1 = mxb1; w2 = mxw2; b2 = mxb2; }
    else if (u < 32) { r = u - 16; src_r = r;      gen = 1; w1 = myw1; b1 = myb1; w2 = myw2; b2 = myb2; }
    else if (u < 40) { r = u - 32; src_r = 16 + r; gen = 2; w1 = axw1; b1 = axb1; w2 = axw2; b2 = axb2; }
    else             { r = u - 40; src_r = 16 + r; gen = 3; w1 = ayw1; b1 = ayb1; w2 = ayw2; b2 = ayb2; }
    w1 += r * HD * HD; b1 += r * HD; w2 += r * HD * NC; b2 += r * NC;

    for (int i = tid; i < HD * 16; i += 256) {
        int d = i >> 4, bb = i & 15;
        fin[d * 20 + bb] = g_rf_t[(src_r * HD + d) * NB + b0 + bb];
    }
    __syncthreads();

    ull acc[8];
#pragma unroll
    for (int j = 0; j < 8; j++) acc[j] = 0ull;
    const float* w1p = w1 + tid;
#pragma unroll 4
    for (int d = 0; d < HD; d++) {
        float w = w1p[d * HD];
        ull wp = pk2(w, w);
        const float4* xr = (const float4*)(fin + d * 20);
        float4 x0 = xr[0], x1 = xr[1], x2 = xr[2], x3 = xr[3];
        fma2(acc[0], wp, pk2(x0.x, x0.y)); fma2(acc[1], wp, pk2(x0.z, x0.w));
        fma2(acc[2], wp, pk2(x1.x, x1.y)); fma2(acc[3], wp, pk2(x1.z, x1.w));
        fma2(acc[4], wp, pk2(x2.x, x2.y)); fma2(acc[5], wp, pk2(x2.z, x2.w));
        fma2(acc[6], wp, pk2(x3.x, x3.y)); fma2(acc[7], wp, pk2(x3.z, x3.w));
    }
    float bias = b1[tid];
#pragma unroll
    for (int j = 0; j < 8; j++) {
        float2 p = up2(acc[j]);
        float2 o = make_float2(lk(p.x + bias), lk(p.y + bias));
        *(float2*)(hdn + tid * 20 + 2 * j) = o;
    }
    __syncthreads();

    // layer2: 16 bb x 24 c = 384 outputs
    for (int o = tid; o < 16 * NC; o += 256) {
        int bb = o / NC, c = o - bb * NC;
        float a = b2[c];
        const float* wp = w2 + c;
#pragma unroll 4
        for (int k = 0; k < HD; k++)
            a = fmaf(wp[k * NC], hdn[k * 20 + bb], a);
        g_cp[((gen * NB + b0 + bb) * 16 + r) * NC + c] = a;
    }
}

// ---------------- K4: splines + weighted reductions ----------------
// grid 2176 blocks of 128: [0,1024) u(b,r); [1024,2048) v(b,r) scaled by softmax(mult);
// [2048,2112) dx(b); [2112,2176) dy(b)+gbias
__global__ void __launch_bounds__(128) k4(const float* __restrict__ mw,
                                          const float* __restrict__ axw,
                                          const float* __restrict__ ayw,
                                          const float* __restrict__ gb) {
    __shared__ __align__(16) float cps[8][24];
    __shared__ float wg[16];
    int tid = threadIdx.x, x = blockIdx.x;

    if (x < 2048) {
        int isv = x >> 10;
        int xx = x & 1023;
        int b = xx >> 4, r = xx & 15;
        const float* cp = g_cp + ((isv * NB + b) * 16 + r) * NC;
        if (tid < NC) cps[0][tid] = cp[tid];
        if (tid == 0) {
            if (isv) {
                float mx = mw[0];
                for (int i = 1; i < 16; i++) mx = fmaxf(mx, mw[i]);
                float s = 0.f, er = 0.f;
                for (int i = 0; i < 16; i++) { float e = expf(mw[i] - mx); s += e; if (i == r) er = e; }
                wg[0] = er / s;
            } else wg[0] = 1.f;
        }
        __syncthreads();
        float sc = wg[0];
        float o[4];
#pragma unroll
        for (int i = 0; i < 4; i++) {
            int w = tid * 4 + i;
            int seg; float h00, h10, h01, h11;
            hcoef(w, seg, h00, h10, h01, h11);
            o[i] = sc * hermev(cps[0], seg, h00, h10, h01, h11);
        }
        float* op = (isv ? g_v : g_u) + (b * 16 + r) * WOUT + tid * 4;
        *(float4*)op = make_float4(o[0], o[1], o[2], o[3]);
    } else {
        int isy = (x >= 2112);
        int b = x - (isy ? 2112 : 2048);
        int gen = 2 + isy;
        for (int i = tid; i < 8 * NC; i += 128) {
            int rr = i / NC, c = i - rr * NC;
            cps[rr][c] = g_cp[((gen * NB + b) * 16 + rr) * NC + c];
        }
        if (tid == 0) {
            const float* ww = isy ? ayw : axw;
            float mx = ww[0];
            for (int i = 1; i < 8; i++) mx = fmaxf(mx, ww[i]);
            float s = 0.f, e[8];
            for (int i = 0; i < 8; i++) { e[i] = expf(ww[i] - mx); s += e[i]; }
            for (int i = 0; i < 8; i++) wg[i] = e[i] / s;
        }
        __syncthreads();
        float base = isy ? gb[0] : 0.f;
        float o[4];
#pragma unroll
        for (int i = 0; i < 4; i++) {
            int w = tid * 4 + i;
            int seg; float h00, h10, h01, h11;
            hcoef(w, seg, h00, h10, h01, h11);
            float a = base;
#pragma unroll
            for (int rr = 0; rr < 8; rr++)
                a = fmaf(wg[rr], hermev(cps[rr], seg, h00, h10, h01, h11), a);
            o[i] = a;
        }
        float* op = (isy ? g_dy : g_dx) + b * WOUT + tid * 4;
        *(float4*)op = make_float4(o[0], o[1], o[2], o[3]);
    }
}

// ---------------- K5: depth[b][h][w] = sum_r wv[b,r,h]*u[b,r,w] + dx + dy ----------------
// grid (16 h-tiles of 32, 64 b), block 128; thread owns a w-quad; u register-resident.
__global__ void __launch_bounds__(128) k5(float* __restrict__ out) {
    __shared__ __align__(16) float2 wv[32][17];  // duplicated coef pairs, padded
    __shared__ float dys[32];
    int tid = threadIdx.x;
    int ht = blockIdx.x, b = blockIdx.y;
    int h0 = ht * 32;

    for (int i = tid; i < 512; i += 128) {
        int r = i >> 5, hh = i & 31;
        float v = g_v[(b * 16 + r) * WOUT + h0 + hh];
        wv[hh][r] = make_float2(v, v);
    }
    if (tid < 32) dys[tid] = g_dy[b * WOUT + h0 + tid];

    int w = tid * 4;
    ull ur2[32];
#pragma unroll
    for (int r = 0; r < 16; r++) {
        float4 t = *(const float4*)(g_u + (b * 16 + r) * WOUT + w);
        ur2[2 * r]     = pk2(t.x, t.y);
        ur2[2 * r + 1] = pk2(t.z, t.w);
    }
    float4 dx4 = *(const float4*)(g_dx + b * WOUT + w);
    __syncthreads();

    float* op = out + (size_t)b * (512 * 512) + (size_t)h0 * 512 + w;
#pragma unroll 2
    for (int hh = 0; hh < 32; hh++) {
        float dyv = dys[hh];
        ull a0 = pk2(dx4.x + dyv, dx4.y + dyv);
        ull a1 = pk2(dx4.z + dyv, dx4.w + dyv);
#pragma unroll
        for (int r = 0; r < 16; r++) {
            ull c2 = *(const ull*)(&wv[hh][r]);
            fma2(a0, c2, ur2[2 * r]);
            fma2(a1, c2, ur2[2 * r + 1]);
        }
        float2 lo = up2(a0), hi = up2(a1);
        *(float4*)(op + hh * 512) = make_float4(lo.x, lo.y, hi.x, hi.y);
    }
}

// ---------------- launch ----------------
extern "C" void kernel_launch(void* const* d_in, const int* in_sizes, int n_in,
                              void* d_out, int out_size) {
    const float* h_in   = (const float*)d_in[0];
    const float* remb   = (const float*)d_in[1];
    const float* st_w1  = (const float*)d_in[2];
    const float* st_b1  = (const float*)d_in[3];
    const float* st_w2  = (const float*)d_in[4];
    const float* st_b2  = (const float*)d_in[5];
    const float* rm_w1  = (const float*)d_in[6];
    const float* rm_b1  = (const float*)d_in[7];
    const float* rm_w2  = (const float*)d_in[8];
    const float* rm_b2  = (const float*)d_in[9];
    const float* mx_w1  = (const float*)d_in[10];
    const float* mx_b1  = (const float*)d_in[11];
    const float* mx_w2  = (const float*)d_in[12];
    const float* mx_b2  = (const float*)d_in[13];
    const float* my_w1  = (const float*)d_in[14];
    const float* my_b1  = (const float*)d_in[15];
    const float* my_w2  = (const float*)d_in[16];
    const float* my_b2  = (const float*)d_in[17];
    const float* ax_w1  = (const float*)d_in[18];
    const float* ax_b1  = (const float*)d_in[19];
    const float* ax_w2  = (const float*)d_in[20];
    const float* ax_b2  = (const float*)d_in[21];
    const float* ay_w1  = (const float*)d_in[22];
    const float* ay_b1  = (const float*)d_in[23];
    const float* ay_w2  = (const float*)d_in[24];
    const float* ay_b2  = (const float*)d_in[25];
    const float* mult_w = (const float*)d_in[26];
    const float* addx_w = (const float*)d_in[27];
    const float* addy_w = (const float*)d_in[28];
    const float* gbias  = (const float*)d_in[29];
    float* out = (float*)d_out;

    k1a<<<dim3(8, 8), 256>>>(h_in, st_w1, st_b1);
    k1b<<<dim3(4, 8), 256>>>(st_w2, st_b2);
    k2 <<<dim3(4, 24), 256>>>(remb, rm_w1, rm_b1, rm_w2, rm_b2);
    k3 <<<dim3(4, 48), 256>>>(mx_w1, mx_b1, mx_w2, mx_b2,
                              my_w1, my_b1, my_w2, my_b2,
                              ax_w1, ax_b1, ax_w2, ax_b2,
                              ay_w1, ay_b1, ay_w2, ay_b2);
    k4 <<<2176, 128>>>(mult_w, addx_w, addy_w, gbias);
    k5 <<<dim3(16, 64), 128>>>(out);
}

// round 3
// speedup vs baseline: 1.9500x; 1.9500x over previous
#include <cuda_runtime.h>

// ---------------- problem constants ----------------
#define NB   64      // batch
#define DIN  768
#define HD   256
#define H2   512     // 2*HD
#define RT   24
#define RMM  16
#define RAA  8
#define NC   24      // control points
#define WOUT 512     // spline output size (H_OUT == W_OUT == 512)

// ---------------- scratch (device globals; no runtime alloc) ----------------
__device__ float g_hid[NB * H2];                 // trunk hidden [b][h2]
__device__ float g_shared_t[HD * NB];            // shared feat TRANSPOSED [c][b]
__device__ float g_rf_t[RT * HD * NB];           // rank feats TRANSPOSED [r][h][b]
__device__ float g_cp[4 * NB * 16 * NC];         // [gen][b][r][c]
__device__ float g_u[NB * RMM * WOUT];           // u splines [b][r][w]
__device__ float g_v[NB * RMM * WOUT];           // v splines pre-scaled by softmax(mult_w)[r]
__device__ float g_dx[NB * WOUT];                // dx[b][w]
__device__ float g_dy[NB * WOUT];                // dy[b][h] + gbias folded in

// ---------------- helpers ----------------
typedef unsigned long long ull;

__device__ __forceinline__ ull pk2(float x, float y) {
    ull r; asm("mov.b64 %0, {%1,%2};" : "=l"(r) : "f"(x), "f"(y)); return r;
}
__device__ __forceinline__ void fma2(ull& d, ull a, ull b) {
    asm("fma.rn.f32x2 %0, %1, %2, %0;" : "+l"(d) : "l"(a), "l"(b));
}
__device__ __forceinline__ ull add2(ull a, ull b) {
    ull r; asm("add.rn.f32x2 %0, %1, %2;" : "=l"(r) : "l"(a), "l"(b)); return r;
}
__device__ __forceinline__ float2 up2(ull a) {
    float2 r; asm("mov.b64 {%0,%1}, %2;" : "=f"(r.x), "=f"(r.y) : "l"(a)); return r;
}
__device__ __forceinline__ float lk(float x) { return x >= 0.f ? x : 0.2f * x; }

// Hermite spline coefficients for output index w (out 512, N=24 cps, nseg=23)
__device__ __forceinline__ void hcoef(int w, int& seg,
                                      float& h00, float& h10, float& h01, float& h11) {
    const float step = 0.998f / 511.f;
    float t  = 0.001f + (float)w * step;
    float ts = t * 23.f;
    int s = (int)floorf(ts);
    s = s < 0 ? 0 : (s > 22 ? 22 : s);
    float tau = ts - (float)s;
    tau = fminf(fmaxf(tau, 0.f), 0.9999f);
    float t2 = tau * tau, t3 = t2 * tau;
    h00 = 2.f * t3 - 3.f * t2 + 1.f;
    h10 = t3 - 2.f * t2 + tau;
    h01 = -2.f * t3 + 3.f * t2;
    h11 = t3 - t2;
    seg = s;
}
__device__ __forceinline__ float hermev(const float* cp, int s,
                                        float h00, float h10, float h01, float h11) {
    const float inv = 0.5f / 23.f;
    float pk  = cp[s];
    float pk1 = cp[s + 1];
    int jm = s - 1; if (jm < 0) jm = 0;
    float mk = (cp[s + 1] - cp[jm]) * inv;
    int j2 = s + 2; if (j2 > 23) j2 = 23;
    float mk1 = (cp[j2] - cp[s]) * inv;
    return h00 * pk + h10 * mk + h01 * pk1 + h11 * mk1;
}

// ---------------- K1a: hidden = leaky(h @ st_w1 + st_b1) ----------------
// grid (8 h-chunks of 64, 8 b-tiles of 8), block 512 = 64 cols x 8 K-splits
__global__ void __launch_bounds__(512) k1a(const float* __restrict__ hin,
                                           const float* __restrict__ w1,
                                           const float* __restrict__ b1) {
    __shared__ __align__(16) float sm[DIN * 12];     // 36 KB: x transposed [d][bb], pad 12
    int tid = threadIdx.x;
    int c = tid & 63, ks = tid >> 6;                 // ks in [0,8)
    int hc = blockIdx.x, btile = blockIdx.y;
    int b0 = btile * 8;
    int hcol = hc * 64 + c;

    for (int i = tid; i < 8 * DIN; i += 512) {       // bb = i/768, d = i%768
        int bb = i / DIN, d = i - bb * DIN;
        sm[d * 12 + bb] = hin[(b0 + bb) * DIN + d];
    }
    __syncthreads();

    ull acc[4];
#pragma unroll
    for (int j = 0; j < 4; j++) acc[j] = 0ull;
    const float* w1p = w1 + hcol;
    int d0 = ks * 96;
#pragma unroll 4
    for (int dd = 0; dd < 96; dd++) {
        int d = d0 + dd;
        float w = w1p[d * H2];
        ull wp = pk2(w, w);
        const ulonglong2* xr = (const ulonglong2*)(sm + d * 12);
        ulonglong2 p0 = xr[0], p1 = xr[1];
        fma2(acc[0], wp, p0.x); fma2(acc[1], wp, p0.y);
        fma2(acc[2], wp, p1.x); fma2(acc[3], wp, p1.y);
    }
    __syncthreads();
    ull* part = (ull*)sm;                            // 512*4 ull = 16 KB overlay
#pragma unroll
    for (int j = 0; j < 4; j++) part[tid * 4 + j] = acc[j];
    __syncthreads();
    if (tid < 256) {
        int cc = tid & 63, j = tid >> 6;             // pair j in [0,4)
        ull s = part[(cc) * 4 + j];
#pragma unroll
        for (int k = 1; k < 8; k++) s = add2(s, part[(k * 64 + cc) * 4 + j]);
        int hco = hc * 64 + cc;
        float2 p = up2(s);
        float bias = b1[hco];
        g_hid[(b0 + 2 * j) * H2 + hco]     = lk(p.x + bias);
        g_hid[(b0 + 2 * j + 1) * H2 + hco] = lk(p.y + bias);
    }
}

// ---------------- K1b: shared_t[c][b] = hidden @ st_w2 + st_b2 ----------------
// grid (4 c-chunks of 64, 16 b-tiles of 4), block 512 = 64 cols x 8 K-splits
__global__ void __launch_bounds__(512) k1b(const float* __restrict__ w2,
                                           const float* __restrict__ b2) {
    __shared__ __align__(16) float sm[H2 * 8];       // 16 KB: [d][bb], 4 used + pad
    int tid = threadIdx.x;
    int c = tid & 63, ks = tid >> 6;
    int cc = blockIdx.x, btile = blockIdx.y;
    int b0 = btile * 4;
    int ccol = cc * 64 + c;

    for (int i = tid; i < 4 * H2; i += 512) {
        int bb = i >> 9, d = i & 511;
        sm[d * 8 + bb] = g_hid[(b0 + bb) * H2 + d];
    }
    __syncthreads();

    ull acc[2] = {0ull, 0ull};
    const float* wp2 = w2 + ccol;
    int d0 = ks * 64;
#pragma unroll 4
    for (int dd = 0; dd < 64; dd++) {
        int d = d0 + dd;
        float w = wp2[d * HD];
        ull wp = pk2(w, w);
        ulonglong2 p0 = *(const ulonglong2*)(sm + d * 8);
        fma2(acc[0], wp, p0.x); fma2(acc[1], wp, p0.y);
    }
    __syncthreads();
    ull* part = (ull*)sm;                            // 1024 ull = 8 KB overlay
    part[tid * 2 + 0] = acc[0];
    part[tid * 2 + 1] = acc[1];
    __syncthreads();
    if (tid < 128) {
        int c2 = tid & 63, j = tid >> 6;             // pair j in [0,2)
        ull s = part[c2 * 2 + j];
#pragma unroll
        for (int k = 1; k < 8; k++) s = add2(s, part[(k * 64 + c2) * 2 + j]);
        int co = cc * 64 + c2;
        float2 p = up2(s);
        float bias = b2[co];
        g_shared_t[co * NB + b0 + 2 * j]     = p.x + bias;
        g_shared_t[co * NB + b0 + 2 * j + 1] = p.y + bias;
    }
}

// ---------------- K2: rank feature gens (24 ranks) ----------------
// grid (4 b-tiles of 16, 24 ranks), block 512 = 256 cols x 2 K-splits
__global__ void __launch_bounds__(512) k2(const float* __restrict__ remb,
                                          const float* __restrict__ w1,
                                          const float* __restrict__ b1,
                                          const float* __restrict__ w2,
                                          const float* __restrict__ b2) {
    __shared__ __align__(16) float sm[H2 * 20];      // 40 KB
    int tid = threadIdx.x;
    int col = tid & 255, ks = tid >> 8;
    int btile = blockIdx.x, r = blockIdx.y;
    int b0 = btile * 16;

    // comb[d][bb], stride 20 (rows 16B aligned)
    for (int i = tid; i < H2 * 16; i += 512) {
        int d = i >> 4, bb = i & 15;
        float v = (d < HD) ? g_shared_t[d * NB + b0 + bb] : remb[r * HD + (d - HD)];
        sm[d * 20 + bb] = v;
    }
    __syncthreads();

    ull acc[8];
#pragma unroll
    for (int j = 0; j < 8; j++) acc[j] = 0ull;
    const float* w1p = w1 + r * H2 * HD + col;
    int d0 = ks * 256;
#pragma unroll 4
    for (int dd = 0; dd < 256; dd++) {
        int d = d0 + dd;
        float w = w1p[d * HD];
        ull wp = pk2(w, w);
        const ulonglong2* xr = (const ulonglong2*)(sm + d * 20);
        ulonglong2 p0 = xr[0], p1 = xr[1], p2 = xr[2], p3 = xr[3];
        fma2(acc[0], wp, p0.x); fma2(acc[1], wp, p0.y);
        fma2(acc[2], wp, p1.x); fma2(acc[3], wp, p1.y);
        fma2(acc[4], wp, p2.x); fma2(acc[5], wp, p2.y);
        fma2(acc[6], wp, p3.x); fma2(acc[7], wp, p3.y);
    }
    __syncthreads();
    ull* part = (ull*)sm;                            // [0, 16KB) overlay
    if (ks == 1) {
#pragma unroll
        for (int j = 0; j < 8; j++) part[col * 8 + j] = acc[j];
    }
    __syncthreads();
    float* hdn = sm + 4096;                          // 256 rows x 20, [16KB, 36KB)
    if (ks == 0) {
        float bias = b1[r * HD + col];
#pragma unroll
        for (int j = 0; j < 8; j++) {
            ull s = add2(acc[j], part[col * 8 + j]);
            float2 p = up2(s);
            *(float2*)(hdn + col * 20 + 2 * j) =
                make_float2(lk(p.x + bias), lk(p.y + bias));
        }
    }
    __syncthreads();

    // layer 2: K = 256, split 2
#pragma unroll
    for (int j = 0; j < 8; j++) acc[j] = 0ull;
    const float* w2p = w2 + r * HD * HD + col;
    int k0 = ks * 128;
#pragma unroll 4
    for (int kk = 0; kk < 128; kk++) {
        int k = k0 + kk;
        float w = w2p[k * HD];
        ull wp = pk2(w, w);
        const ulonglong2* xr = (const ulonglong2*)(hdn + k * 20);
        ulonglong2 p0 = xr[0], p1 = xr[1], p2 = xr[2], p3 = xr[3];
        fma2(acc[0], wp, p0.x); fma2(acc[1], wp, p0.y);
        fma2(acc[2], wp, p1.x); fma2(acc[3], wp, p1.y);
        fma2(acc[4], wp, p2.x); fma2(acc[5], wp, p2.y);
        fma2(acc[6], wp, p3.x); fma2(acc[7], wp, p3.y);
    }
    __syncthreads();
    if (ks == 1) {
#pragma unroll
        for (int j = 0; j < 8; j++) part[col * 8 + j] = acc[j];
    }
    __syncthreads();
    if (ks == 0) {
        float bias2 = b2[r * HD + col];
        float* o = g_rf_t + (r * HD + col) * NB + b0;
#pragma unroll
        for (int j = 0; j < 8; j++) {
            ull s = add2(acc[j], part[col * 8 + j]);
            float2 p = up2(s);
            *(float2*)(o + 2 * j) = make_float2(p.x + bias2, p.y + bias2);
        }
    }
}

// ---------------- K3: control-point gens (mx/my/ax/ay), 48 units ----------------
// grid (4 b-tiles of 16, 48 units), block 512 = 256 cols x 2 K-splits
__global__ void __launch_bounds__(512) k3(
        const float* __restrict__ mxw1, const float* __restrict__ mxb1,
        const float* __restrict__ mxw2, const float* __restrict__ mxb2,
        const float* __restrict__ myw1, const float* __restrict__ myb1,
        const float* __restrict__ myw2, const float* __restrict__ myb2,
        const float* __restrict__ axw1, const float* __restrict__ axb1,
        const float* __restrict__ axw2, const float* __restrict__ axb2,
        const float* __restrict__ ayw1, const float* __restrict__ ayb1,
        const float* __restrict__ ayw2, const float* __restrict__ ayb2) {
    __shared__ __align__(16) float sm[HD * 40];      // 40 KB: fin [0,20KB), hdn [20KB,40KB)
    int tid = threadIdx.x;
    int col = tid & 255, ks = tid >> 8;
    int btile = blockIdx.x, u = blockIdx.y;
    int b0 = btile * 16;

    const float *w1, *b1, *w2, *b2;
    int r, src_r, gen;
    if (u < 16)      { r = u;      src_r = u;      gen = 0; w1 = mxw1; b1 = mxb1; w2 = mxw2; b2 = mxb2; }
    else if (u < 32) { r = u - 16; src_r = r;      gen = 1; w1 = myw1; b1 = myb1; w2 = myw2; b2 = myb2; }
    else if (u < 40) { r = u - 32; src_r = 16 + r; gen = 2; w1 = axw1; b1 = axb1; w2 = axw2; b2 = axb2; }
    else             { r = u - 40; src_r = 16 + r; gen = 3; w1 = ayw1; b1 = ayb1; w2 = ayw2; b2 = ayb2; }
    w1 += r * HD * HD; b1 += r * HD; w2 += r * HD * NC; b2 += r * NC;

    for (int i = tid; i < HD * 16; i += 512) {
        int d = i >> 4, bb = i & 15;
        sm[d * 20 + bb] = g_rf_t[(src_r * HD + d) * NB + b0 + bb];
    }
    __syncthreads();

    ull acc[8];
#pragma unroll
    for (int j = 0; j < 8; j++) acc[j] = 0ull;
    const float* w1p = w1 + col;
    int d0 = ks * 128;
#pragma unroll 4
    for (int dd = 0; dd < 128; dd++) {
        int d = d0 + dd;
        float w = w1p[d * HD];
        ull wp = pk2(w, w);
        const ulonglong2* xr = (const ulonglong2*)(sm + d * 20);
        ulonglong2 p0 = xr[0], p1 = xr[1], p2 = xr[2], p3 = xr[3];
        fma2(acc[0], wp, p0.x); fma2(acc[1], wp, p0.y);
        fma2(acc[2], wp, p1.x); fma2(acc[3], wp, p1.y);
        fma2(acc[4], wp, p2.x); fma2(acc[5], wp, p2.y);
        fma2(acc[6], wp, p3.x); fma2(acc[7], wp, p3.y);
    }
    __syncthreads();
    ull* part = (ull*)sm;                            // [0, 16KB) overlay on fin
    if (ks == 1) {
#pragma unroll
        for (int j = 0; j < 8; j++) part[col * 8 + j] = acc[j];
    }
    __syncthreads();
    float* hdn = sm + 5120;                          // [20KB, 40KB)
    if (ks == 0) {
        float bias = b1[col];
#pragma unroll
        for (int j = 0; j < 8; j++) {
            ull s = add2(acc[j], part[col * 8 + j]);
            float2 p = up2(s);
            *(float2*)(hdn + col * 20 + 2 * j) =
                make_float2(lk(p.x + bias), lk(p.y + bias));
        }
    }
    __syncthreads();

    // layer2: 16 bb x 24 c = 384 outputs, full K per thread
    if (tid < 16 * NC) {
        int bb = tid / NC, c = tid - bb * NC;
        float a = b2[c];
        const float* wp = w2 + c;
#pragma unroll 4
        for (int k = 0; k < HD; k++)
            a = fmaf(wp[k * NC], hdn[k * 20 + bb], a);
        g_cp[((gen * NB + b0 + bb) * 16 + r) * NC + c] = a;
    }
}

// ---------------- K4: splines + weighted reductions ----------------
__global__ void __launch_bounds__(128) k4(const float* __restrict__ mw,
                                          const float* __restrict__ axw,
                                          const float* __restrict__ ayw,
                                          const float* __restrict__ gb) {
    __shared__ __align__(16) float cps[8][24];
    __shared__ float wg[16];
    int tid = threadIdx.x, x = blockIdx.x;

    if (x < 2048) {
        int isv = x >> 10;
        int xx = x & 1023;
        int b = xx >> 4, r = xx & 15;
        const float* cp = g_cp + ((isv * NB + b) * 16 + r) * NC;
        if (tid < NC) cps[0][tid] = cp[tid];
        if (tid == 0) {
            if (isv) {
                float mx = mw[0];
                for (int i = 1; i < 16; i++) mx = fmaxf(mx, mw[i]);
                float s = 0.f, er = 0.f;
                for (int i = 0; i < 16; i++) { float e = expf(mw[i] - mx); s += e; if (i == r) er = e; }
                wg[0] = er / s;
            } else wg[0] = 1.f;
        }
        __syncthreads();
        float sc = wg[0];
        float o[4];
#pragma unroll
        for (int i = 0; i < 4; i++) {
            int w = tid * 4 + i;
            int seg; float h00, h10, h01, h11;
            hcoef(w, seg, h00, h10, h01, h11);
            o[i] = sc * hermev(cps[0], seg, h00, h10, h01, h11);
        }
        float* op = (isv ? g_v : g_u) + (b * 16 + r) * WOUT + tid * 4;
        *(float4*)op = make_float4(o[0], o[1], o[2], o[3]);
    } else {
        int isy = (x >= 2112);
        int b = x - (isy ? 2112 : 2048);
        int gen = 2 + isy;
        for (int i = tid; i < 8 * NC; i += 128) {
            int rr = i / NC, c = i - rr * NC;
            cps[rr][c] = g_cp[((gen * NB + b) * 16 + rr) * NC + c];
        }
        if (tid == 0) {
            const float* ww = isy ? ayw : axw;
            float mx = ww[0];
            for (int i = 1; i < 8; i++) mx = fmaxf(mx, ww[i]);
            float s = 0.f, e[8];
            for (int i = 0; i < 8; i++) { e[i] = expf(ww[i] - mx); s += e[i]; }
            for (int i = 0; i < 8; i++) wg[i] = e[i] / s;
        }
        __syncthreads();
        float base = isy ? gb[0] : 0.f;
        float o[4];
#pragma unroll
        for (int i = 0; i < 4; i++) {
            int w = tid * 4 + i;
            int seg; float h00, h10, h01, h11;
            hcoef(w, seg, h00, h10, h01, h11);
            float a = base;
#pragma unroll
            for (int rr = 0; rr < 8; rr++)
                a = fmaf(wg[rr], hermev(cps[rr], seg, h00, h10, h01, h11), a);
            o[i] = a;
        }
        float* op = (isy ? g_dy : g_dx) + b * WOUT + tid * 4;
        *(float4*)op = make_float4(o[0], o[1], o[2], o[3]);
    }
}

// ---------------- K5: depth[b][h][w] = sum_r wv[b,r,h]*u[b,r,w] + dx + dy ----------------
// grid (16 h-tiles of 32, 64 b), block 128; u register-resident; v pairs packed in rows
__global__ void __launch_bounds__(128) k5(float* __restrict__ out) {
    __shared__ __align__(16) float wv[32][36];       // row: 16 dup pairs (32 floats) + pad
    __shared__ float dys[32];
    int tid = threadIdx.x;
    int ht = blockIdx.x, b = blockIdx.y;
    int h0 = ht * 32;

    for (int i = tid; i < 512; i += 128) {
        int r = i >> 5, hh = i & 31;
        float v = g_v[(b * 16 + r) * WOUT + h0 + hh];
        wv[hh][2 * r] = v;
        wv[hh][2 * r + 1] = v;
    }
    if (tid < 32) dys[tid] = g_dy[b * WOUT + h0 + tid];

    int w = tid * 4;
    ull ur2[32];
#pragma unroll
    for (int r = 0; r < 16; r++) {
        float4 t = *(const float4*)(g_u + (b * 16 + r) * WOUT + w);
        ur2[2 * r]     = pk2(t.x, t.y);
        ur2[2 * r + 1] = pk2(t.z, t.w);
    }
    float4 dx4 = *(const float4*)(g_dx + b * WOUT + w);
    ull dxp0 = pk2(dx4.x, dx4.y), dxp1 = pk2(dx4.z, dx4.w);
    __syncthreads();

    float* op = out + (size_t)b * (512 * 512) + (size_t)h0 * 512 + w;
#pragma unroll 2
    for (int hh = 0; hh < 32; hh++) {
        float dyv = dys[hh];
        ull dyp = pk2(dyv, dyv);
        ull a0 = add2(dxp0, dyp);
        ull a1 = add2(dxp1, dyp);
        const ulonglong2* row = (const ulonglong2*)&wv[hh][0];
#pragma unroll
        for (int i = 0; i < 8; i++) {
            ulonglong2 c = row[i];
            fma2(a0, c.x, ur2[4 * i]);
            fma2(a1, c.x, ur2[4 * i + 1]);
            fma2(a0, c.y, ur2[4 * i + 2]);
            fma2(a1, c.y, ur2[4 * i + 3]);
        }
        float2 lo = up2(a0), hi = up2(a1);
        *(float4*)(op + hh * 512) = make_float4(lo.x, lo.y, hi.x, hi.y);
    }
}

// ---------------- launch ----------------
extern "C" void kernel_launch(void* const* d_in, const int* in_sizes, int n_in,
                              void* d_out, int out_size) {
    const float* h_in   = (const float*)d_in[0];
    const float* remb   = (const float*)d_in[1];
    const float* st_w1  = (const float*)d_in[2];
    const float* st_b1  = (const float*)d_in[3];
    const float* st_w2  = (const float*)d_in[4];
    const float* st_b2  = (const float*)d_in[5];
    const float* rm_w1  = (const float*)d_in[6];
    const float* rm_b1  = (const float*)d_in[7];
    const float* rm_w2  = (const float*)d_in[8];
    const float* rm_b2  = (const float*)d_in[9];
    const float* mx_w1  = (const float*)d_in[10];
    const float* mx_b1  = (const float*)d_in[11];
    const float* mx_w2  = (const float*)d_in[12];
    const float* mx_b2  = (const float*)d_in[13];
    const float* my_w1  = (const float*)d_in[14];
    const float* my_b1  = (const float*)d_in[15];
    const float* my_w2  = (const float*)d_in[16];
    const float* my_b2  = (const float*)d_in[17];
    const float* ax_w1  = (const float*)d_in[18];
    const float* ax_b1  = (const float*)d_in[19];
    const float* ax_w2  = (const float*)d_in[20];
    const float* ax_b2  = (const float*)d_in[21];
    const float* ay_w1  = (const float*)d_in[22];
    const float* ay_b1  = (const float*)d_in[23];
    const float* ay_w2  = (const float*)d_in[24];
    const float* ay_b2  = (const float*)d_in[25];
    const float* mult_w = (const float*)d_in[26];
    const float* addx_w = (const float*)d_in[27];
    const float* addy_w = (const float*)d_in[28];
    const float* gbias  = (const float*)d_in[29];
    float* out = (float*)d_out;

    k1a<<<dim3(8, 8), 512>>>(h_in, st_w1, st_b1);
    k1b<<<dim3(4, 16), 512>>>(st_w2, st_b2);
    k2 <<<dim3(4, 24), 512>>>(remb, rm_w1, rm_b1, rm_w2, rm_b2);
    k3 <<<dim3(4, 48), 512>>>(mx_w1, mx_b1, mx_w2, mx_b2,
                              my_w1, my_b1, my_w2, my_b2,
                              ax_w1, ax_b1, ax_w2, ax_b2,
                              ay_w1, ay_b1, ay_w2, ay_b2);
    k4 <<<2176, 128>>>(mult_w, addx_w, addy_w, gbias);
    k5 <<<dim3(16, 64), 128>>>(out);
}

// round 6
// speedup vs baseline: 2.6533x; 1.3607x over previous
#include <cuda_runtime.h>

// ---------------- problem constants ----------------
#define NB   64      // batch
#define DIN  768
#define HD   256
#define H2   512     // 2*HD
#define RT   24
#define NC   24      // control points
#define WOUT 512

// ---------------- scratch (device globals; no runtime alloc) ----------------
__device__ float g_hid[NB * H2];                 // trunk hidden [b][h2]
__device__ float g_shared_t[HD * NB];            // shared feat TRANSPOSED [c][b]
__device__ float g_hdn[RT * HD * NB];            // k2 hidden (post-act) [r][k][b]
__device__ float g_rf_t[RT * HD * NB];           // rank feats TRANSPOSED [r][h][b]
__device__ float g_hdn3[48 * HD * NB];           // k3 hidden (post-act) [u][k][b]
__device__ float g_cp[4 * NB * 16 * NC];         // [gen][b][r][c]
__device__ float g_u[NB * 16 * WOUT];            // u splines [b][r][w]
__device__ float g_v[NB * 16 * WOUT];            // v splines pre-scaled by softmax(mult_w)
__device__ float g_dx[NB * WOUT];
__device__ float g_dy[NB * WOUT];                // dy + gbias folded in

// ---------------- helpers ----------------
typedef unsigned long long ull;

__device__ __forceinline__ ull pk2(float x, float y) {
    ull r; asm("mov.b64 %0, {%1,%2};" : "=l"(r) : "f"(x), "f"(y)); return r;
}
__device__ __forceinline__ void fma2(ull& d, ull a, ull b) {
    asm("fma.rn.f32x2 %0, %1, %2, %0;" : "+l"(d) : "l"(a), "l"(b));
}
__device__ __forceinline__ ull add2(ull a, ull b) {
    ull r; asm("add.rn.f32x2 %0, %1, %2;" : "=l"(r) : "l"(a), "l"(b)); return r;
}
__device__ __forceinline__ float2 up2(ull a) {
    float2 r; asm("mov.b64 {%0,%1}, %2;" : "=f"(r.x), "=f"(r.y) : "l"(a)); return r;
}
__device__ __forceinline__ float lk(float x) { return x >= 0.f ? x : 0.2f * x; }

__device__ __forceinline__ void hcoef(int w, int& seg,
                                      float& h00, float& h10, float& h01, float& h11) {
    const float step = 0.998f / 511.f;
    float t  = 0.001f + (float)w * step;
    float ts = t * 23.f;
    int s = (int)floorf(ts);
    s = s < 0 ? 0 : (s > 22 ? 22 : s);
    float tau = ts - (float)s;
    tau = fminf(fmaxf(tau, 0.f), 0.9999f);
    float t2 = tau * tau, t3 = t2 * tau;
    h00 = 2.f * t3 - 3.f * t2 + 1.f;
    h10 = t3 - 2.f * t2 + tau;
    h01 = -2.f * t3 + 3.f * t2;
    h11 = t3 - t2;
    seg = s;
}
__device__ __forceinline__ float hermev(const float* cp, int s,
                                        float h00, float h10, float h01, float h11) {
    const float inv = 0.5f / 23.f;
    float pk  = cp[s];
    float pk1 = cp[s + 1];
    int jm = s - 1; if (jm < 0) jm = 0;
    float mk = (cp[s + 1] - cp[jm]) * inv;
    int j2 = s + 2; if (j2 > 23) j2 = 23;
    float mk1 = (cp[j2] - cp[s]) * inv;
    return h00 * pk + h10 * mk + h01 * pk1 + h11 * mk1;
}

// ============ GEMM core macro: 4 cols x 8 batch, fp32x2 ============
// acc[c*4 + p]: col c (0..3), batch-pair p (0..3)
#define GEMM_STEP(WPTR, XPTR)                                           \
    {                                                                   \
        float4 wv = *(const float4*)(WPTR);                             \
        ulonglong2 xa = *(const ulonglong2*)(XPTR);                     \
        ulonglong2 xb = *(const ulonglong2*)((XPTR) + 4);               \
        ull w0 = pk2(wv.x, wv.x), w1q = pk2(wv.y, wv.y);                \
        ull w2q = pk2(wv.z, wv.z), w3q = pk2(wv.w, wv.w);               \
        fma2(acc[0],  w0,  xa.x); fma2(acc[1],  w0,  xa.y);             \
        fma2(acc[2],  w0,  xb.x); fma2(acc[3],  w0,  xb.y);             \
        fma2(acc[4],  w1q, xa.x); fma2(acc[5],  w1q, xa.y);             \
        fma2(acc[6],  w1q, xb.x); fma2(acc[7],  w1q, xb.y);             \
        fma2(acc[8],  w2q, xa.x); fma2(acc[9],  w2q, xa.y);             \
        fma2(acc[10], w2q, xb.x); fma2(acc[11], w2q, xb.y);             \
        fma2(acc[12], w3q, xa.x); fma2(acc[13], w3q, xa.y);             \
        fma2(acc[14], w3q, xb.x); fma2(acc[15], w3q, xb.y);             \
    }

// 8-way K-split pair-tree reduction over smem buffer `part` (>= 16 KB).
// quad in [0,32), ks in [0,8). On exit ks==0 threads hold the full sum.
#define KSPLIT8_REDUCE(part)                                            \
    __syncthreads();                                                    \
    if (ks >= 4) {                                                      \
        ull* w = (part) + (((ks - 4) * 32 + quad) << 4);                \
        _Pragma("unroll") for (int j = 0; j < 16; j++) w[j] = acc[j];   \
    }                                                                   \
    __syncthreads();                                                    \
    if (ks < 4) {                                                       \
        ull* rd = (part) + ((ks * 32 + quad) << 4);                     \
        _Pragma("unroll") for (int j = 0; j < 16; j++)                  \
            acc[j] = add2(acc[j], rd[j]);                               \
    }                                                                   \
    __syncthreads();                                                    \
    if (ks == 2 || ks == 3) {                                           \
        ull* w = (part) + (((ks - 2) * 32 + quad) << 4);                \
        _Pragma("unroll") for (int j = 0; j < 16; j++) w[j] = acc[j];   \
    }                                                                   \
    __syncthreads();                                                    \
    if (ks < 2) {                                                       \
        ull* rd = (part) + ((ks * 32 + quad) << 4);                     \
        _Pragma("unroll") for (int j = 0; j < 16; j++)                  \
            acc[j] = add2(acc[j], rd[j]);                               \
    }                                                                   \
    __syncthreads();                                                    \
    if (ks == 1) {                                                      \
        ull* w = (part) + (quad << 4);                                  \
        _Pragma("unroll") for (int j = 0; j < 16; j++) w[j] = acc[j];   \
    }                                                                   \
    __syncthreads();                                                    \
    if (ks == 0) {                                                      \
        ull* rd = (part) + (quad << 4);                                 \
        _Pragma("unroll") for (int j = 0; j < 16; j++)                  \
            acc[j] = add2(acc[j], rd[j]);                               \
    }

// ---------------- K1a: hidden = leaky(h @ st_w1 + st_b1) ----------------
__global__ void __launch_bounds__(512) k1a(const float* __restrict__ hin,
                                           const float* __restrict__ w1,
                                           const float* __restrict__ b1) {
    __shared__ __align__(16) float sm[DIN * 12];
    int tid = threadIdx.x;
    int c = tid & 63, ks = tid >> 6;
    int hc = blockIdx.x, btile = blockIdx.y;
    int b0 = btile * 8;
    int hcol = hc * 64 + c;

    for (int i = tid; i < 8 * DIN; i += 512) {
        int bb = i / DIN, d = i - bb * DIN;
        sm[d * 12 + bb] = hin[(b0 + bb) * DIN + d];
    }
    __syncthreads();

    ull acc[4];
#pragma unroll
    for (int j = 0; j < 4; j++) acc[j] = 0ull;
    const float* w1p = w1 + hcol;
    int d0 = ks * 96;
#pragma unroll 4
    for (int dd = 0; dd < 96; dd++) {
        int d = d0 + dd;
        float w = w1p[d * H2];
        ull wp = pk2(w, w);
        const ulonglong2* xr = (const ulonglong2*)(sm + d * 12);
        ulonglong2 p0 = xr[0], p1 = xr[1];
        fma2(acc[0], wp, p0.x); fma2(acc[1], wp, p0.y);
        fma2(acc[2], wp, p1.x); fma2(acc[3], wp, p1.y);
    }
    __syncthreads();
    ull* part = (ull*)sm;
#pragma unroll
    for (int j = 0; j < 4; j++) part[tid * 4 + j] = acc[j];
    __syncthreads();
    if (tid < 256) {
        int cc = tid & 63, j = tid >> 6;
        ull s = part[cc * 4 + j];
#pragma unroll
        for (int k = 1; k < 8; k++) s = add2(s, part[(k * 64 + cc) * 4 + j]);
        int hco = hc * 64 + cc;
        float2 p = up2(s);
        float bias = b1[hco];
        g_hid[(b0 + 2 * j) * H2 + hco]     = lk(p.x + bias);
        g_hid[(b0 + 2 * j + 1) * H2 + hco] = lk(p.y + bias);
    }
}

// ---------------- K1b: shared_t = hidden @ st_w2 + st_b2 ----------------
__global__ void __launch_bounds__(512) k1b(const float* __restrict__ w2,
                                           const float* __restrict__ b2) {
    __shared__ __align__(16) float sm[H2 * 8];
    int tid = threadIdx.x;
    int c = tid & 63, ks = tid >> 6;
    int cc = blockIdx.x, btile = blockIdx.y;
    int b0 = btile * 4;
    int ccol = cc * 64 + c;

    for (int i = tid; i < 4 * H2; i += 512) {
        int bb = i >> 9, d = i & 511;
        sm[d * 8 + bb] = g_hid[(b0 + bb) * H2 + d];
    }
    __syncthreads();

    ull acc[2] = {0ull, 0ull};
    const float* wp2 = w2 + ccol;
    int d0 = ks * 64;
#pragma unroll 4
    for (int dd = 0; dd < 64; dd++) {
        int d = d0 + dd;
        float w = wp2[d * HD];
        ull wp = pk2(w, w);
        ulonglong2 p0 = *(const ulonglong2*)(sm + d * 8);
        fma2(acc[0], wp, p0.x); fma2(acc[1], wp, p0.y);
    }
    __syncthreads();
    ull* part = (ull*)sm;
    part[tid * 2 + 0] = acc[0];
    part[tid * 2 + 1] = acc[1];
    __syncthreads();
    if (tid < 128) {
        int c2 = tid & 63, j = tid >> 6;
        ull s = part[c2 * 2 + j];
#pragma unroll
        for (int k = 1; k < 8; k++) s = add2(s, part[(k * 64 + c2) * 2 + j]);
        int co = cc * 64 + c2;
        float2 p = up2(s);
        float bias = b2[co];
        g_shared_t[co * NB + b0 + 2 * j]     = p.x + bias;
        g_shared_t[co * NB + b0 + 2 * j + 1] = p.y + bias;
    }
}

// ---------------- K2a: rank-gen layer1 ----------------
// grid (2 colhalf x 8 btile = 16, 24 r), block 256 = 32 quads x 8 ksplit (K chunk 64)
__global__ void __launch_bounds__(256) k2a(const float* __restrict__ remb,
                                           const float* __restrict__ w1,
                                           const float* __restrict__ b1) {
    __shared__ __align__(16) float comb[H2 * 8];   // 16 KB; partials overlay after use
    int tid = threadIdx.x;
    int quad = tid & 31, ks = tid >> 5;
    int ch = blockIdx.x & 1, btile = blockIdx.x >> 1;
    int r = blockIdx.y;
    int b0 = btile * 8;
    int col0 = ch * 128 + quad * 4;

    for (int i = tid; i < H2 * 8; i += 256) {
        int d = i >> 3, bb = i & 7;
        comb[i] = (d < HD) ? g_shared_t[d * NB + b0 + bb] : remb[r * HD + (d - HD)];
    }
    __syncthreads();

    ull acc[16];
#pragma unroll
    for (int j = 0; j < 16; j++) acc[j] = 0ull;
    const float* wp = w1 + (r * H2 + ks * 64) * HD + col0;
    const float* xp = comb + (ks * 64) * 8;
#pragma unroll 4
    for (int dd = 0; dd < 64; dd++) {
        GEMM_STEP(wp, xp);
        wp += HD; xp += 8;
    }

    ull* part = (ull*)comb;
    KSPLIT8_REDUCE(part);
    if (ks == 0) {
#pragma unroll
        for (int c = 0; c < 4; c++) {
            int col = col0 + c;
            float bias = b1[r * HD + col];
            float2 p0 = up2(acc[c * 4 + 0]), p1 = up2(acc[c * 4 + 1]);
            float2 p2 = up2(acc[c * 4 + 2]), p3 = up2(acc[c * 4 + 3]);
            float* o = g_hdn + (r * HD + col) * NB + b0;
            *(float4*)o = make_float4(lk(p0.x + bias), lk(p0.y + bias),
                                      lk(p1.x + bias), lk(p1.y + bias));
            *(float4*)(o + 4) = make_float4(lk(p2.x + bias), lk(p2.y + bias),
                                            lk(p3.x + bias), lk(p3.y + bias));
        }
    }
}

// ---------------- K2b: rank-gen layer2 ----------------
// grid (16, 24), block 256 = 32 quads x 8 ksplit (K chunk 32)
__global__ void __launch_bounds__(256) k2b(const float* __restrict__ w2,
                                           const float* __restrict__ b2) {
    __shared__ __align__(16) float hdnl[HD * 8];   // 8 KB
    __shared__ __align__(16) ull partbuf[128 * 16];// 16 KB
    int tid = threadIdx.x;
    int quad = tid & 31, ks = tid >> 5;
    int ch = blockIdx.x & 1, btile = blockIdx.x >> 1;
    int r = blockIdx.y;
    int b0 = btile * 8;
    int col0 = ch * 128 + quad * 4;

    for (int i = tid; i < HD * 8; i += 256) {
        int k = i >> 3, bb = i & 7;
        hdnl[i] = g_hdn[(r * HD + k) * NB + b0 + bb];
    }
    __syncthreads();

    ull acc[16];
#pragma unroll
    for (int j = 0; j < 16; j++) acc[j] = 0ull;
    const float* wp = w2 + (r * HD + ks * 32) * HD + col0;
    const float* xp = hdnl + (ks * 32) * 8;
#pragma unroll 4
    for (int kk = 0; kk < 32; kk++) {
        GEMM_STEP(wp, xp);
        wp += HD; xp += 8;
    }

    KSPLIT8_REDUCE(partbuf);
    if (ks == 0) {
#pragma unroll
        for (int c = 0; c < 4; c++) {
            int col = col0 + c;
            float bias = b2[r * HD + col];
            float2 p0 = up2(acc[c * 4 + 0]), p1 = up2(acc[c * 4 + 1]);
            float2 p2 = up2(acc[c * 4 + 2]), p3 = up2(acc[c * 4 + 3]);
            float* o = g_rf_t + (r * HD + col) * NB + b0;
            *(float4*)o = make_float4(p0.x + bias, p0.y + bias,
                                      p1.x + bias, p1.y + bias);
            *(float4*)(o + 4) = make_float4(p2.x + bias, p2.y + bias,
                                            p3.x + bias, p3.y + bias);
        }
    }
}

// ---------------- K3a: cp-gen layer1 (48 units) ----------------
// grid (16, 48), block 256 = 32 quads x 8 ksplit (K chunk 32)
__global__ void __launch_bounds__(256) k3a(
        const float* __restrict__ mxw1, const float* __restrict__ mxb1,
        const float* __restrict__ myw1, const float* __restrict__ myb1,
        const float* __restrict__ axw1, const float* __restrict__ axb1,
        const float* __restrict__ ayw1, const float* __restrict__ ayb1) {
    __shared__ __align__(16) float fin[HD * 8];    // 8 KB
    __shared__ __align__(16) ull partbuf[128 * 16];// 16 KB
    int tid = threadIdx.x;
    int quad = tid & 31, ks = tid >> 5;
    int ch = blockIdx.x & 1, btile = blockIdx.x >> 1;
    int u = blockIdx.y;
    int b0 = btile * 8;
    int col0 = ch * 128 + quad * 4;

    const float *w1, *b1;
    int r, src_r;
    if (u < 16)      { r = u;      src_r = u;      w1 = mxw1; b1 = mxb1; }
    else if (u < 32) { r = u - 16; src_r = r;      w1 = myw1; b1 = myb1; }
    else if (u < 40) { r = u - 32; src_r = 16 + r; w1 = axw1; b1 = axb1; }
    else             { r = u - 40; src_r = 16 + r; w1 = ayw1; b1 = ayb1; }
    w1 += r * HD * HD; b1 += r * HD;

    for (int i = tid; i < HD * 8; i += 256) {
        int k = i >> 3, bb = i & 7;
        fin[i] = g_rf_t[(src_r * HD + k) * NB + b0 + bb];
    }
    __syncthreads();

    ull acc[16];
#pragma unroll
    for (int j = 0; j < 16; j++) acc[j] = 0ull;
    const float* wp = w1 + (ks * 32) * HD + col0;
    const float* xp = fin + (ks * 32) * 8;
#pragma unroll 4
    for (int kk = 0; kk < 32; kk++) {
        GEMM_STEP(wp, xp);
        wp += HD; xp += 8;
    }

    KSPLIT8_REDUCE(partbuf);
    if (ks == 0) {
#pragma unroll
        for (int c = 0; c < 4; c++) {
            int col = col0 + c;
            float bias = b1[col];
            float2 p0 = up2(acc[c * 4 + 0]), p1 = up2(acc[c * 4 + 1]);
            float2 p2 = up2(acc[c * 4 + 2]), p3 = up2(acc[c * 4 + 3]);
            float* o = g_hdn3 + (u * HD + col) * NB + b0;
            *(float4*)o = make_float4(lk(p0.x + bias), lk(p0.y + bias),
                                      lk(p1.x + bias), lk(p1.y + bias));
            *(float4*)(o + 4) = make_float4(lk(p2.x + bias), lk(p2.y + bias),
                                            lk(p3.x + bias), lk(p3.y + bias));
        }
    }
}

// ---------------- K3b: cp-gen layer2 -> control points ----------------
// grid (48 units, 6 cgroups), block 256 = 64 b x 4 c
__global__ void __launch_bounds__(256) k3b(
        const float* __restrict__ mxw2, const float* __restrict__ mxb2,
        const float* __restrict__ myw2, const float* __restrict__ myb2,
        const float* __restrict__ axw2, const float* __restrict__ axb2,
        const float* __restrict__ ayw2, const float* __restrict__ ayb2) {
    __shared__ __align__(16) float wcol[HD * 4];   // 4 KB
    int tid = threadIdx.x;
    int b = tid & 63, ci = tid >> 6;
    int u = blockIdx.x, cg = blockIdx.y;
    int c = cg * 4 + ci;

    const float *w2, *b2;
    int r, gen;
    if (u < 16)      { r = u;      gen = 0; w2 = mxw2; b2 = mxb2; }
    else if (u < 32) { r = u - 16; gen = 1; w2 = myw2; b2 = myb2; }
    else if (u < 40) { r = u - 32; gen = 2; w2 = axw2; b2 = axb2; }
    else             { r = u - 40; gen = 3; w2 = ayw2; b2 = ayb2; }
    w2 += r * HD * NC; b2 += r * NC;

    for (int i = tid; i < HD * 4; i += 256) {
        int k = i >> 2, cc = i & 3;
        wcol[i] = w2[k * NC + cg * 4 + cc];
    }
    __syncthreads();

    const float* hp = g_hdn3 + (u * HD) * NB + b;
    float a0 = 0.f, a1 = 0.f, a2 = 0.f, a3 = 0.f;
#pragma unroll 8
    for (int k = 0; k < HD; k += 4) {
        a0 = fmaf(wcol[(k + 0) * 4 + ci], hp[(k + 0) * NB], a0);
        a1 = fmaf(wcol[(k + 1) * 4 + ci], hp[(k + 1) * NB], a1);
        a2 = fmaf(wcol[(k + 2) * 4 + ci], hp[(k + 2) * NB], a2);
        a3 = fmaf(wcol[(k + 3) * 4 + ci], hp[(k + 3) * NB], a3);
    }
    float a = (a0 + a1) + (a2 + a3) + b2[c];
    g_cp[((gen * NB + b) * 16 + r) * NC + c] = a;
}

// ---------------- K4: splines + weighted reductions ----------------
__global__ void __launch_bounds__(128) k4(const float* __restrict__ mw,
                                          const float* __restrict__ axw,
                                          const float* __restrict__ ayw,
                                          const float* __restrict__ gb) {
    __shared__ __align__(16) float cps[8][24];
    __shared__ float wg[16];
    int tid = threadIdx.x, x = blockIdx.x;

    if (x < 2048) {
        int isv = x >> 10;
        int xx = x & 1023;
        int b = xx >> 4, r = xx & 15;
        const float* cp = g_cp + ((isv * NB + b) * 16 + r) * NC;
        if (tid < NC) cps[0][tid] = cp[tid];
        if (tid == 0) {
            if (isv) {
                float mx = mw[0];
                for (int i = 1; i < 16; i++) mx = fmaxf(mx, mw[i]);
                float s = 0.f, er = 0.f;
                for (int i = 0; i < 16; i++) { float e = expf(mw[i] - mx); s += e; if (i == r) er = e; }
                wg[0] = er / s;
            } else wg[0] = 1.f;
        }
        __syncthreads();
        float sc = wg[0];
        float o[4];
#pragma unroll
        for (int i = 0; i < 4; i++) {
            int w = tid * 4 + i;
            int seg; float h00, h10, h01, h11;
            hcoef(w, seg, h00, h10, h01, h11);
            o[i] = sc * hermev(cps[0], seg, h00, h10, h01, h11);
        }
        float* op = (isv ? g_v : g_u) + (b * 16 + r) * WOUT + tid * 4;
        *(float4*)op = make_float4(o[0], o[1], o[2], o[3]);
    } else {
        int isy = (x >= 2112);
        int b = x - (isy ? 2112 : 2048);
        int gen = 2 + isy;
        for (int i = tid; i < 8 * NC; i += 128) {
            int rr = i / NC, c = i - rr * NC;
            cps[rr][c] = g_cp[((gen * NB + b) * 16 + rr) * NC + c];
        }
        if (tid == 0) {
            const float* ww = isy ? ayw : axw;
            float mx = ww[0];
            for (int i = 1; i < 8; i++) mx = fmaxf(mx, ww[i]);
            float s = 0.f, e[8];
            for (int i = 0; i < 8; i++) { e[i] = expf(ww[i] - mx); s += e[i]; }
            for (int i = 0; i < 8; i++) wg[i] = e[i] / s;
        }
        __syncthreads();
        float base = isy ? gb[0] : 0.f;
        float o[4];
#pragma unroll
        for (int i = 0; i < 4; i++) {
            int w = tid * 4 + i;
            int seg; float h00, h10, h01, h11;
            hcoef(w, seg, h00, h10, h01, h11);
            float a = base;
#pragma unroll
            for (int rr = 0; rr < 8; rr++)
                a = fmaf(wg[rr], hermev(cps[rr], seg, h00, h10, h01, h11), a);
            o[i] = a;
        }
        float* op = (isy ? g_dy : g_dx) + b * WOUT + tid * 4;
        *(float4*)op = make_float4(o[0], o[1], o[2], o[3]);
    }
}

// ---------------- K5: depth = sum_r wv*u + dx + dy ----------------
__global__ void __launch_bounds__(128) k5(float* __restrict__ out) {
    __shared__ __align__(16) float wv[32][36];
    __shared__ float dys[32];
    int tid = threadIdx.x;
    int ht = blockIdx.x, b = blockIdx.y;
    int h0 = ht * 32;

    for (int i = tid; i < 512; i += 128) {
        int r = i >> 5, hh = i & 31;
        float v = g_v[(b * 16 + r) * WOUT + h0 + hh];
        wv[hh][2 * r] = v;
        wv[hh][2 * r + 1] = v;
    }
    if (tid < 32) dys[tid] = g_dy[b * WOUT + h0 + tid];

    int w = tid * 4;
    ull ur2[32];
#pragma unroll
    for (int r = 0; r < 16; r++) {
        float4 t = *(const float4*)(g_u + (b * 16 + r) * WOUT + w);
        ur2[2 * r]     = pk2(t.x, t.y);
        ur2[2 * r + 1] = pk2(t.z, t.w);
    }
    float4 dx4 = *(const float4*)(g_dx + b * WOUT + w);
    ull dxp0 = pk2(dx4.x, dx4.y), dxp1 = pk2(dx4.z, dx4.w);
    __syncthreads();

    float* op = out + (size_t)b * (512 * 512) + (size_t)h0 * 512 + w;
#pragma unroll 2
    for (int hh = 0; hh < 32; hh++) {
        float dyv = dys[hh];
        ull dyp = pk2(dyv, dyv);
        ull a0 = add2(dxp0, dyp);
        ull a1 = add2(dxp1, dyp);
        const ulonglong2* row = (const ulonglong2*)&wv[hh][0];
#pragma unroll
        for (int i = 0; i < 8; i++) {
            ulonglong2 c = row[i];
            fma2(a0, c.x, ur2[4 * i]);
            fma2(a1, c.x, ur2[4 * i + 1]);
            fma2(a0, c.y, ur2[4 * i + 2]);
            fma2(a1, c.y, ur2[4 * i + 3]);
        }
        float2 lo = up2(a0), hi = up2(a1);
        *(float4*)(op + hh * 512) = make_float4(lo.x, lo.y, hi.x, hi.y);
    }
}

// ---------------- launch ----------------
extern "C" void kernel_launch(void* const* d_in, const int* in_sizes, int n_in,
                              void* d_out, int out_size) {
    const float* h_in   = (const float*)d_in[0];
    const float* remb   = (const float*)d_in[1];
    const float* st_w1  = (const float*)d_in[2];
    const float* st_b1  = (const float*)d_in[3];
    const float* st_w2  = (const float*)d_in[4];
    const float* st_b2  = (const float*)d_in[5];
    const float* rm_w1  = (const float*)d_in[6];
    const float* rm_b1  = (const float*)d_in[7];
    const float* rm_w2  = (const float*)d_in[8];
    const float* rm_b2  = (const float*)d_in[9];
    const float* mx_w1  = (const float*)d_in[10];
    const float* mx_b1  = (const float*)d_in[11];
    const float* mx_w2  = (const float*)d_in[12];
    const float* mx_b2  = (const float*)d_in[13];
    const float* my_w1  = (const float*)d_in[14];
    const float* my_b1  = (const float*)d_in[15];
    const float* my_w2  = (const float*)d_in[16];
    const float* my_b2  = (const float*)d_in[17];
    const float* ax_w1  = (const float*)d_in[18];
    const float* ax_b1  = (const float*)d_in[19];
    const float* ax_w2  = (const float*)d_in[20];
    const float* ax_b2  = (const float*)d_in[21];
    const float* ay_w1  = (const float*)d_in[22];
    const float* ay_b1  = (const float*)d_in[23];
    const float* ay_w2  = (const float*)d_in[24];
    const float* ay_b2  = (const float*)d_in[25];
    const float* mult_w = (const float*)d_in[26];
    const float* addx_w = (const float*)d_in[27];
    const float* addy_w = (const float*)d_in[28];
    const float* gbias  = (const float*)d_in[29];
    float* out = (float*)d_out;

    k1a<<<dim3(8, 8), 512>>>(h_in, st_w1, st_b1);
    k1b<<<dim3(4, 16), 512>>>(st_w2, st_b2);
    k2a<<<dim3(16, 24), 256>>>(remb, rm_w1, rm_b1);
    k2b<<<dim3(16, 24), 256>>>(rm_w2, rm_b2);
    k3a<<<dim3(16, 48), 256>>>(mx_w1, mx_b1, my_w1, my_b1,
                               ax_w1, ax_b1, ay_w1, ay_b1);
    k3b<<<dim3(48, 6), 256>>>(mx_w2, mx_b2, my_w2, my_b2,
                              ax_w2, ax_b2, ay_w2, ay_b2);
    k4 <<<2176, 128>>>(mult_w, addx_w, addy_w, gbias);
    k5 <<<dim3(16, 64), 128>>>(out);
}

// round 7
// speedup vs baseline: 2.7327x; 1.0299x over previous
#include <cuda_runtime.h>

// ---------------- problem constants ----------------
#define NB   64
#define DIN  768
#define HD   256
#define H2   512
#define NC   24
#define WOUT 512

// ---------------- scratch ----------------
__device__ float g_hid[NB * H2];
__device__ float g_shared_t[HD * NB];            // [c][b]
__device__ float g_rb[24 * HD];                  // rank bias: remb@W1bot + b1
__device__ float g_hdn[24 * HD * NB];            // [r][k][b]
__device__ float g_rf_t[24 * HD * NB];           // [r][h][b]
__device__ float g_hdn3[48 * HD * NB];           // [u][k][b]
__device__ float g_cp[4 * NB * 16 * NC];
__device__ float g_u[NB * 16 * WOUT];
__device__ float g_v[NB * 16 * WOUT];
__device__ float g_dx[NB * WOUT];
__device__ float g_dy[NB * WOUT];

// ---------------- helpers ----------------
typedef unsigned long long ull;

__device__ __forceinline__ ull pk2(float x, float y) {
    ull r; asm("mov.b64 %0, {%1,%2};" : "=l"(r) : "f"(x), "f"(y)); return r;
}
__device__ __forceinline__ void fma2(ull& d, ull a, ull b) {
    asm("fma.rn.f32x2 %0, %1, %2, %0;" : "+l"(d) : "l"(a), "l"(b));
}
__device__ __forceinline__ ull add2(ull a, ull b) {
    ull r; asm("add.rn.f32x2 %0, %1, %2;" : "=l"(r) : "l"(a), "l"(b)); return r;
}
__device__ __forceinline__ float2 up2(ull a) {
    float2 r; asm("mov.b64 {%0,%1}, %2;" : "=f"(r.x), "=f"(r.y) : "l"(a)); return r;
}
__device__ __forceinline__ float lk(float x) { return x >= 0.f ? x : 0.2f * x; }

__device__ __forceinline__ void cpa16(float* sdst, const float* gsrc) {
    unsigned sa = (unsigned)__cvta_generic_to_shared(sdst);
    asm volatile("cp.async.cg.shared.global [%0], [%1], 16;" :: "r"(sa), "l"(gsrc) : "memory");
}
#define CPA_COMMIT() asm volatile("cp.async.commit_group;" ::: "memory")
#define CPA_WAIT1()  asm volatile("cp.async.wait_group 1;" ::: "memory")

__device__ __forceinline__ void hcoef(int w, int& seg,
                                      float& h00, float& h10, float& h01, float& h11) {
    const float step = 0.998f / 511.f;
    float t  = 0.001f + (float)w * step;
    float ts = t * 23.f;
    int s = (int)floorf(ts);
    s = s < 0 ? 0 : (s > 22 ? 22 : s);
    float tau = ts - (float)s;
    tau = fminf(fmaxf(tau, 0.f), 0.9999f);
    float t2 = tau * tau, t3 = t2 * tau;
    h00 = 2.f * t3 - 3.f * t2 + 1.f;
    h10 = t3 - 2.f * t2 + tau;
    h01 = -2.f * t3 + 3.f * t2;
    h11 = t3 - t2;
    seg = s;
}
__device__ __forceinline__ float hermev(const float* cp, int s,
                                        float h00, float h10, float h01, float h11) {
    const float inv = 0.5f / 23.f;
    float pk  = cp[s];
    float pk1 = cp[s + 1];
    int jm = s - 1; if (jm < 0) jm = 0;
    float mk = (cp[s + 1] - cp[jm]) * inv;
    int j2 = s + 2; if (j2 > 23) j2 = 23;
    float mk1 = (cp[j2] - cp[s]) * inv;
    return h00 * pk + h10 * mk + h01 * pk1 + h11 * mk1;
}

// ======== pipelined GEMM body: 64 cols x 32 batch, K=256, w via cp.async ========
// tid: quad = tid&15 (4 cols), bg = tid>>4 (2 batches). acc[4] packed col-pairs.
// xs: [256][32] smem (filled by caller pre-sync). ws: 3 stages x 16 rows x 64 cols.
// wsrc: gmem, row stride HD floats, pre-offset to this block's 64 cols.
__device__ __forceinline__ void gemm_main(const float* __restrict__ wsrc,
                                          const float* xs, float* ws,
                                          ull* acc, int tid) {
    int row = tid >> 4, cseg = tid & 15;
    const float* gseg = wsrc + row * HD + cseg * 4;
    int quad = tid & 15, bg = tid >> 4;

    // prologue already issued chunks 0,1 by caller? No — do it here.
    cpa16(ws + 0 * 1024 + tid * 4, gseg);            CPA_COMMIT();
    cpa16(ws + 1 * 1024 + tid * 4, gseg + 16 * HD);  CPA_COMMIT();
    __syncthreads();                                  // xs ready (caller staged xs before call)

#pragma unroll 1
    for (int c = 0; c < 16; c++) {
        CPA_WAIT1();
        __syncthreads();
        if (c + 2 < 16) cpa16(ws + ((c + 2) % 3) * 1024 + tid * 4, gseg + (c + 2) * 16 * HD);
        CPA_COMMIT();
        const float* wst = ws + (c % 3) * 1024;
        const float* xc  = xs + c * 16 * 32;
#pragma unroll
        for (int kk = 0; kk < 16; kk++) {
            ulonglong2 wp = *(const ulonglong2*)(wst + kk * 64 + quad * 4);
            float2 xv = *(const float2*)(xc + kk * 32 + bg * 2);
            ull x0 = pk2(xv.x, xv.x), x1 = pk2(xv.y, xv.y);
            fma2(acc[0], wp.x, x0); fma2(acc[1], wp.x, x1);
            fma2(acc[2], wp.y, x0); fma2(acc[3], wp.y, x1);
        }
    }
}

// stage x[256][32] from a global [256][64] slab at batch offset b0
__device__ __forceinline__ void stage_x(float* xs, const float* __restrict__ src, int b0, int tid) {
    for (int s = tid; s < 2048; s += 256) {
        int d = s >> 3, seg = s & 7;
        *(ulonglong2*)(xs + d * 32 + seg * 4) =
            *(const ulonglong2*)(src + d * NB + b0 + seg * 4);
    }
}

// ---------------- K1a ----------------
__global__ void __launch_bounds__(512) k1a(const float* __restrict__ hin,
                                           const float* __restrict__ w1,
                                           const float* __restrict__ b1) {
    __shared__ __align__(16) float sm[DIN * 12];
    int tid = threadIdx.x;
    int c = tid & 63, ks = tid >> 6;
    int hc = blockIdx.x, btile = blockIdx.y;
    int b0 = btile * 8;
    int hcol = hc * 64 + c;

    for (int i = tid; i < 8 * DIN; i += 512) {
        int bb = i / DIN, d = i - bb * DIN;
        sm[d * 12 + bb] = hin[(b0 + bb) * DIN + d];
    }
    __syncthreads();

    ull acc[4];
#pragma unroll
    for (int j = 0; j < 4; j++) acc[j] = 0ull;
    const float* w1p = w1 + hcol;
    int d0 = ks * 96;
#pragma unroll 4
    for (int dd = 0; dd < 96; dd++) {
        int d = d0 + dd;
        float w = w1p[d * H2];
        ull wp = pk2(w, w);
        const ulonglong2* xr = (const ulonglong2*)(sm + d * 12);
        ulonglong2 p0 = xr[0], p1 = xr[1];
        fma2(acc[0], wp, p0.x); fma2(acc[1], wp, p0.y);
        fma2(acc[2], wp, p1.x); fma2(acc[3], wp, p1.y);
    }
    __syncthreads();
    ull* part = (ull*)sm;
#pragma unroll
    for (int j = 0; j < 4; j++) part[tid * 4 + j] = acc[j];
    __syncthreads();
    if (tid < 256) {
        int cc = tid & 63, j = tid >> 6;
        ull s = part[cc * 4 + j];
#pragma unroll
        for (int k = 1; k < 8; k++) s = add2(s, part[(k * 64 + cc) * 4 + j]);
        int hco = hc * 64 + cc;
        float2 p = up2(s);
        float bias = b1[hco];
        g_hid[(b0 + 2 * j) * H2 + hco]     = lk(p.x + bias);
        g_hid[(b0 + 2 * j + 1) * H2 + hco] = lk(p.y + bias);
    }
}

// ---------------- K1b ----------------
__global__ void __launch_bounds__(512) k1b(const float* __restrict__ w2,
                                           const float* __restrict__ b2) {
    __shared__ __align__(16) float sm[H2 * 8];
    int tid = threadIdx.x;
    int c = tid & 63, ks = tid >> 6;
    int cc = blockIdx.x, btile = blockIdx.y;
    int b0 = btile * 4;
    int ccol = cc * 64 + c;

    for (int i = tid; i < 4 * H2; i += 512) {
        int bb = i >> 9, d = i & 511;
        sm[d * 8 + bb] = g_hid[(b0 + bb) * H2 + d];
    }
    __syncthreads();

    ull acc[2] = {0ull, 0ull};
    const float* wp2 = w2 + ccol;
    int d0 = ks * 64;
#pragma unroll 4
    for (int dd = 0; dd < 64; dd++) {
        int d = d0 + dd;
        float w = wp2[d * HD];
        ull wp = pk2(w, w);
        ulonglong2 p0 = *(const ulonglong2*)(sm + d * 8);
        fma2(acc[0], wp, p0.x); fma2(acc[1], wp, p0.y);
    }
    __syncthreads();
    ull* part = (ull*)sm;
    part[tid * 2 + 0] = acc[0];
    part[tid * 2 + 1] = acc[1];
    __syncthreads();
    if (tid < 128) {
        int c2 = tid & 63, j = tid >> 6;
        ull s = part[c2 * 2 + j];
#pragma unroll
        for (int k = 1; k < 8; k++) s = add2(s, part[(k * 64 + c2) * 2 + j]);
        int co = cc * 64 + c2;
        float2 p = up2(s);
        float bias = b2[co];
        g_shared_t[co * NB + b0 + 2 * j]     = p.x + bias;
        g_shared_t[co * NB + b0 + 2 * j + 1] = p.y + bias;
    }
}

// ---------------- KRB: g_rb[r][c] = remb_r @ W1_bot + b1 ----------------
// grid 24, block 1024 = 256 cols x 4 ksplit
__global__ void __launch_bounds__(1024) krb(const float* __restrict__ remb,
                                            const float* __restrict__ w1,
                                            const float* __restrict__ b1) {
    __shared__ float part[1024];
    int tid = threadIdx.x;
    int col = tid & 255, ks = tid >> 8;
    int r = blockIdx.x;
    const float* wp = w1 + (r * H2 + HD + ks * 64) * HD + col;
    const float* rp = remb + r * HD + ks * 64;
    float a = 0.f;
#pragma unroll 8
    for (int d = 0; d < 64; d++)
        a = fmaf(__ldg(rp + d), wp[d * HD], a);
    part[tid] = a;
    __syncthreads();
    if (ks == 0) {
        a += part[256 + col] + part[512 + col] + part[768 + col];
        g_rb[r * HD + col] = a + b1[r * HD + col];
    }
}

// ---------------- K2a: hdn = leaky(shared @ W1_top + rb) ----------------
// grid (4 ch, 2 bh, 24 r), block 256
__global__ void __launch_bounds__(256) k2a(const float* __restrict__ w1) {
    __shared__ __align__(16) float xs[HD * 32];   // 32 KB
    __shared__ __align__(16) float ws[3 * 1024];  // 12 KB
    int tid = threadIdx.x;
    int ch = blockIdx.x, bh = blockIdx.y, r = blockIdx.z;
    int b0 = bh * 32;
    const float* wsrc = w1 + (size_t)r * H2 * HD + ch * 64;

    int quad = tid & 15, bg = tid >> 4;
    int col0 = ch * 64 + quad * 4;
    float4 rb = *(const float4*)(g_rb + r * HD + col0);

    stage_x(xs, g_shared_t, b0, tid);

    ull acc[4] = {0ull, 0ull, 0ull, 0ull};
    gemm_main(wsrc, xs, ws, acc, tid);

    float2 a00 = up2(acc[0]), a01 = up2(acc[1]);
    float2 a10 = up2(acc[2]), a11 = up2(acc[3]);
    float* o = g_hdn + (size_t)(r * HD + col0) * NB + b0 + bg * 2;
    *(float2*)(o + 0 * NB) = make_float2(lk(a00.x + rb.x), lk(a01.x + rb.x));
    *(float2*)(o + 1 * NB) = make_float2(lk(a00.y + rb.y), lk(a01.y + rb.y));
    *(float2*)(o + 2 * NB) = make_float2(lk(a10.x + rb.z), lk(a11.x + rb.z));
    *(float2*)(o + 3 * NB) = make_float2(lk(a10.y + rb.w), lk(a11.y + rb.w));
}

// ---------------- K2b: rf = hdn @ W2 + b2 ----------------
__global__ void __launch_bounds__(256) k2b(const float* __restrict__ w2,
                                           const float* __restrict__ b2) {
    __shared__ __align__(16) float xs[HD * 32];
    __shared__ __align__(16) float ws[3 * 1024];
    int tid = threadIdx.x;
    int ch = blockIdx.x, bh = blockIdx.y, r = blockIdx.z;
    int b0 = bh * 32;
    const float* wsrc = w2 + (size_t)r * HD * HD + ch * 64;

    int quad = tid & 15, bg = tid >> 4;
    int col0 = ch * 64 + quad * 4;
    float4 bias = *(const float4*)(b2 + r * HD + col0);

    stage_x(xs, g_hdn + (size_t)r * HD * NB, b0, tid);

    ull acc[4] = {0ull, 0ull, 0ull, 0ull};
    gemm_main(wsrc, xs, ws, acc, tid);

    float2 a00 = up2(acc[0]), a01 = up2(acc[1]);
    float2 a10 = up2(acc[2]), a11 = up2(acc[3]);
    float* o = g_rf_t + (size_t)(r * HD + col0) * NB + b0 + bg * 2;
    *(float2*)(o + 0 * NB) = make_float2(a00.x + bias.x, a01.x + bias.x);
    *(float2*)(o + 1 * NB) = make_float2(a00.y + bias.y, a01.y + bias.y);
    *(float2*)(o + 2 * NB) = make_float2(a10.x + bias.z, a11.x + bias.z);
    *(float2*)(o + 3 * NB) = make_float2(a10.y + bias.w, a11.y + bias.w);
}

// ---------------- K3a: cp-gen layer1, 48 units ----------------
// grid (4 ch, 2 bh, 48 u), block 256
__global__ void __launch_bounds__(256) k3a(
        const float* __restrict__ mxw1, const float* __restrict__ mxb1,
        const float* __restrict__ myw1, const float* __restrict__ myb1,
        const float* __restrict__ axw1, const float* __restrict__ axb1,
        const float* __restrict__ ayw1, const float* __restrict__ ayb1) {
    __shared__ __align__(16) float xs[HD * 32];
    __shared__ __align__(16) float ws[3 * 1024];
    int tid = threadIdx.x;
    int ch = blockIdx.x, bh = blockIdx.y, u = blockIdx.z;
    int b0 = bh * 32;

    const float *w1, *b1;
    int r, src_r;
    if (u < 16)      { r = u;      src_r = u;      w1 = mxw1; b1 = mxb1; }
    else if (u < 32) { r = u - 16; src_r = r;      w1 = myw1; b1 = myb1; }
    else if (u < 40) { r = u - 32; src_r = 16 + r; w1 = axw1; b1 = axb1; }
    else             { r = u - 40; src_r = 16 + r; w1 = ayw1; b1 = ayb1; }
    const float* wsrc = w1 + (size_t)r * HD * HD + ch * 64;

    int quad = tid & 15, bg = tid >> 4;
    int col0 = ch * 64 + quad * 4;
    float4 bias = *(const float4*)(b1 + r * HD + col0);

    stage_x(xs, g_rf_t + (size_t)src_r * HD * NB, b0, tid);

    ull acc[4] = {0ull, 0ull, 0ull, 0ull};
    gemm_main(wsrc, xs, ws, acc, tid);

    float2 a00 = up2(acc[0]), a01 = up2(acc[1]);
    float2 a10 = up2(acc[2]), a11 = up2(acc[3]);
    float* o = g_hdn3 + (size_t)(u * HD + col0) * NB + b0 + bg * 2;
    *(float2*)(o + 0 * NB) = make_float2(lk(a00.x + bias.x), lk(a01.x + bias.x));
    *(float2*)(o + 1 * NB) = make_float2(lk(a00.y + bias.y), lk(a01.y + bias.y));
    *(float2*)(o + 2 * NB) = make_float2(lk(a10.x + bias.z), lk(a11.x + bias.z));
    *(float2*)(o + 3 * NB) = make_float2(lk(a10.y + bias.w), lk(a11.y + bias.w));
}

// ---------------- K3b ----------------
__global__ void __launch_bounds__(256) k3b(
        const float* __restrict__ mxw2, const float* __restrict__ mxb2,
        const float* __restrict__ myw2, const float* __restrict__ myb2,
        const float* __restrict__ axw2, const float* __restrict__ axb2,
        const float* __restrict__ ayw2, const float* __restrict__ ayb2) {
    __shared__ __align__(16) float wcol[HD * 4];
    int tid = threadIdx.x;
    int b = tid & 63, ci = tid >> 6;
    int u = blockIdx.x, cg = blockIdx.y;
    int c = cg * 4 + ci;

    const float *w2, *b2;
    int r, gen;
    if (u < 16)      { r = u;      gen = 0; w2 = mxw2; b2 = mxb2; }
    else if (u < 32) { r = u - 16; gen = 1; w2 = myw2; b2 = myb2; }
    else if (u < 40) { r = u - 32; gen = 2; w2 = axw2; b2 = axb2; }
    else             { r = u - 40; gen = 3; w2 = ayw2; b2 = ayb2; }
    w2 += r * HD * NC; b2 += r * NC;

    for (int i = tid; i < HD * 4; i += 256) {
        int k = i >> 2, cc = i & 3;
        wcol[i] = w2[k * NC + cg * 4 + cc];
    }
    __syncthreads();

    const float* hp = g_hdn3 + (size_t)(u * HD) * NB + b;
    float a0 = 0.f, a1 = 0.f, a2 = 0.f, a3 = 0.f;
#pragma unroll 8
    for (int k = 0; k < HD; k += 4) {
        a0 = fmaf(wcol[(k + 0) * 4 + ci], hp[(k + 0) * NB], a0);
        a1 = fmaf(wcol[(k + 1) * 4 + ci], hp[(k + 1) * NB], a1);
        a2 = fmaf(wcol[(k + 2) * 4 + ci], hp[(k + 2) * NB], a2);
        a3 = fmaf(wcol[(k + 3) * 4 + ci], hp[(k + 3) * NB], a3);
    }
    float a = (a0 + a1) + (a2 + a3) + b2[c];
    g_cp[((gen * NB + b) * 16 + r) * NC + c] = a;
}

// ---------------- K4 ----------------
__global__ void __launch_bounds__(128) k4(const float* __restrict__ mw,
                                          const float* __restrict__ axw,
                                          const float* __restrict__ ayw,
                                          const float* __restrict__ gb) {
    __shared__ __align__(16) float cps[8][24];
    __shared__ float wg[16];
    int tid = threadIdx.x, x = blockIdx.x;

    if (x < 2048) {
        int isv = x >> 10;
        int xx = x & 1023;
        int b = xx >> 4, r = xx & 15;
        const float* cp = g_cp + ((isv * NB + b) * 16 + r) * NC;
        if (tid < NC) cps[0][tid] = cp[tid];
        if (tid == 0) {
            if (isv) {
                float mx = mw[0];
                for (int i = 1; i < 16; i++) mx = fmaxf(mx, mw[i]);
                float s = 0.f, er = 0.f;
                for (int i = 0; i < 16; i++) { float e = expf(mw[i] - mx); s += e; if (i == r) er = e; }
                wg[0] = er / s;
            } else wg[0] = 1.f;
        }
        __syncthreads();
        float sc = wg[0];
        float o[4];
#pragma unroll
        for (int i = 0; i < 4; i++) {
            int w = tid * 4 + i;
            int seg; float h00, h10, h01, h11;
            hcoef(w, seg, h00, h10, h01, h11);
            o[i] = sc * hermev(cps[0], seg, h00, h10, h01, h11);
        }
        float* op = (isv ? g_v : g_u) + (b * 16 + r) * WOUT + tid * 4;
        *(float4*)op = make_float4(o[0], o[1], o[2], o[3]);
    } else {
        int isy = (x >= 2112);
        int b = x - (isy ? 2112 : 2048);
        int gen = 2 + isy;
        for (int i = tid; i < 8 * NC; i += 128) {
            int rr = i / NC, c = i - rr * NC;
            cps[rr][c] = g_cp[((gen * NB + b) * 16 + rr) * NC + c];
        }
        if (tid == 0) {
            const float* ww = isy ? ayw : axw;
            float mx = ww[0];
            for (int i = 1; i < 8; i++) mx = fmaxf(mx, ww[i]);
            float s = 0.f, e[8];
            for (int i = 0; i < 8; i++) { e[i] = expf(ww[i] - mx); s += e[i]; }
            for (int i = 0; i < 8; i++) wg[i] = e[i] / s;
        }
        __syncthreads();
        float base = isy ? gb[0] : 0.f;
        float o[4];
#pragma unroll
        for (int i = 0; i < 4; i++) {
            int w = tid * 4 + i;
            int seg; float h00, h10, h01, h11;
            hcoef(w, seg, h00, h10, h01, h11);
            float a = base;
#pragma unroll
            for (int rr = 0; rr < 8; rr++)
                a = fmaf(wg[rr], hermev(cps[rr], seg, h00, h10, h01, h11), a);
            o[i] = a;
        }
        float* op = (isy ? g_dy : g_dx) + b * WOUT + tid * 4;
        *(float4*)op = make_float4(o[0], o[1], o[2], o[3]);
    }
}

// ---------------- K5 ----------------
__global__ void __launch_bounds__(128) k5(float* __restrict__ out) {
    __shared__ __align__(16) float wv[32][36];
    __shared__ float dys[32];
    int tid = threadIdx.x;
    int ht = blockIdx.x, b = blockIdx.y;
    int h0 = ht * 32;

    for (int i = tid; i < 512; i += 128) {
        int r = i >> 5, hh = i & 31;
        float v = g_v[(b * 16 + r) * WOUT + h0 + hh];
        wv[hh][2 * r] = v;
        wv[hh][2 * r + 1] = v;
    }
    if (tid < 32) dys[tid] = g_dy[b * WOUT + h0 + tid];

    int w = tid * 4;
    ull ur2[32];
#pragma unroll
    for (int r = 0; r < 16; r++) {
        float4 t = *(const float4*)(g_u + (b * 16 + r) * WOUT + w);
        ur2[2 * r]     = pk2(t.x, t.y);
        ur2[2 * r + 1] = pk2(t.z, t.w);
    }
    float4 dx4 = *(const float4*)(g_dx + b * WOUT + w);
    ull dxp0 = pk2(dx4.x, dx4.y), dxp1 = pk2(dx4.z, dx4.w);
    __syncthreads();

    float* op = out + (size_t)b * (512 * 512) + (size_t)h0 * 512 + w;
#pragma unroll 2
    for (int hh = 0; hh < 32; hh++) {
        float dyv = dys[hh];
        ull dyp = pk2(dyv, dyv);
        ull a0 = add2(dxp0, dyp);
        ull a1 = add2(dxp1, dyp);
        const ulonglong2* row = (const ulonglong2*)&wv[hh][0];
#pragma unroll
        for (int i = 0; i < 8; i++) {
            ulonglong2 c = row[i];
            fma2(a0, c.x, ur2[4 * i]);
            fma2(a1, c.x, ur2[4 * i + 1]);
            fma2(a0, c.y, ur2[4 * i + 2]);
            fma2(a1, c.y, ur2[4 * i + 3]);
        }
        float2 lo = up2(a0), hi = up2(a1);
        *(float4*)(op + hh * 512) = make_float4(lo.x, lo.y, hi.x, hi.y);
    }
}

// ---------------- launch ----------------
extern "C" void kernel_launch(void* const* d_in, const int* in_sizes, int n_in,
                              void* d_out, int out_size) {
    const float* h_in   = (const float*)d_in[0];
    const float* remb   = (const float*)d_in[1];
    const float* st_w1  = (const float*)d_in[2];
    const float* st_b1  = (const float*)d_in[3];
    const float* st_w2  = (const float*)d_in[4];
    const float* st_b2  = (const float*)d_in[5];
    const float* rm_w1  = (const float*)d_in[6];
    const float* rm_b1  = (const float*)d_in[7];
    const float* rm_w2  = (const float*)d_in[8];
    const float* rm_b2  = (const float*)d_in[9];
    const float* mx_w1  = (const float*)d_in[10];
    const float* mx_b1  = (const float*)d_in[11];
    const float* mx_w2  = (const float*)d_in[12];
    const float* mx_b2  = (const float*)d_in[13];
    const float* my_w1  = (const float*)d_in[14];
    const float* my_b1  = (const float*)d_in[15];
    const float* my_w2  = (const float*)d_in[16];
    const float* my_b2  = (const float*)d_in[17];
    const float* ax_w1  = (const float*)d_in[18];
    const float* ax_b1  = (const float*)d_in[19];
    const float* ax_w2  = (const float*)d_in[20];
    const float* ax_b2  = (const float*)d_in[21];
    const float* ay_w1  = (const float*)d_in[22];
    const float* ay_b1  = (const float*)d_in[23];
    const float* ay_w2  = (const float*)d_in[24];
    const float* ay_b2  = (const float*)d_in[25];
    const float* mult_w = (const float*)d_in[26];
    const float* addx_w = (const float*)d_in[27];
    const float* addy_w = (const float*)d_in[28];
    const float* gbias  = (const float*)d_in[29];
    float* out = (float*)d_out;

    krb<<<24, 1024>>>(remb, rm_w1, rm_b1);
    k1a<<<dim3(8, 8), 512>>>(h_in, st_w1, st_b1);
    k1b<<<dim3(4, 16), 512>>>(st_w2, st_b2);
    k2a<<<dim3(4, 2, 24), 256>>>(rm_w1);
    k2b<<<dim3(4, 2, 24), 256>>>(rm_w2, rm_b2);
    k3a<<<dim3(4, 2, 48), 256>>>(mx_w1, mx_b1, my_w1, my_b1,
                                 ax_w1, ax_b1, ay_w1, ay_b1);
    k3b<<<dim3(48, 6), 256>>>(mx_w2, mx_b2, my_w2, my_b2,
                              ax_w2, ax_b2, ay_w2, ay_b2);
    k4<<<2176, 128>>>(mult_w, addx_w, addy_w, gbias);
    k5<<<dim3(16, 64), 128>>>(out);
}